// round 8
// baseline (speedup 1.0000x reference)
#include <cuda_runtime.h>

#define IMG 224
#define NPIX (IMG * IMG)        // 50176
#define NUM_VIEWS 6
#define NBATCH 16
#define NBV (NBATCH * NUM_VIEWS)   // 96
#define NPTS 32768
#define THREADS 1024
#define NGROUPS (NPTS / 4)         // 8192 float4-groups of 4 points
#define NITERS (NGROUPS / THREADS) // 8 iterations in the splat kernel

// Per-(b,v) monotone-encoded min/max of z_fin
__device__ unsigned g_zmin_u[NBV];
__device__ unsigned g_zmax_u[NBV];

// monotone float<->uint mapping (order-preserving for all finite floats)
__device__ __forceinline__ unsigned f2mono(float f) {
    unsigned b = __float_as_uint(f);
    return (b & 0x80000000u) ? ~b : (b | 0x80000000u);
}
__device__ __forceinline__ float mono2f(unsigned u) {
    unsigned b = (u & 0x80000000u) ? (u & 0x7fffffffu) : ~u;
    return __uint_as_float(b);
}

__global__ void init_kernel() {
    int i = threadIdx.x;
    if (i < NBV) {
        g_zmin_u[i] = 0xFFFFFFFFu;
        g_zmax_u[i] = 0u;
    }
}

// 4 CTAs per (b,v); each reduces a quarter of the points.
#define RED_SPLIT 4
#define RED_THREADS 256
__global__ __launch_bounds__(RED_THREADS)
void reduce_kernel(const float* __restrict__ points) {
    const int cta = blockIdx.x;
    const int bv  = cta >> 2;            // / RED_SPLIT
    const int sub = cta & 3;
    const int b   = bv / NUM_VIEWS;
    const int v   = bv % NUM_VIEWS;
    const int tid = threadIdx.x;

    const float deg2rad = 0.017453292519943295f;
    const float a = (float)(v * 60) * deg2rad;
    const float el_tab[NUM_VIEWS] = {0.f, 30.f, -30.f, 0.f, 0.f, 0.f};
    const float e = el_tab[v] * deg2rad;
    const float sa = sinf(a), ca = cosf(a), ce = cosf(e), se = sinf(e);
    const float kx = sa * ce, ky = se, kz = ca * ce;   // fused z_fin coeffs

    const int gpc = NGROUPS / RED_SPLIT;               // 2048 groups per CTA
    const float4* __restrict__ pb4 =
        (const float4*)(points + (size_t)b * NPTS * 3) + (size_t)3 * sub * gpc;

    float zmn = INFINITY, zmx = -INFINITY;
    #pragma unroll 1
    for (int g = tid; g < gpc; g += RED_THREADS) {
        float4 p0 = pb4[3 * g + 0];
        float4 p1 = pb4[3 * g + 1];
        float4 p2 = pb4[3 * g + 2];
        float xs[4] = {p0.x, p0.w, p1.z, p2.y};
        float ys[4] = {p0.y, p1.x, p1.w, p2.z};
        float zs[4] = {p0.z, p1.y, p2.x, p2.w};
        #pragma unroll
        for (int k = 0; k < 4; k++) {
            float zf = xs[k] * kx + ys[k] * ky + zs[k] * kz;
            zmn = fminf(zmn, zf);
            zmx = fmaxf(zmx, zf);
        }
    }
    #pragma unroll
    for (int o = 16; o > 0; o >>= 1) {
        zmn = fminf(zmn, __shfl_xor_sync(0xffffffffu, zmn, o));
        zmx = fmaxf(zmx, __shfl_xor_sync(0xffffffffu, zmx, o));
    }
    __shared__ float smn[8], smx[8];
    const int wid = tid >> 5, lid = tid & 31;
    if (lid == 0) { smn[wid] = zmn; smx[wid] = zmx; }
    __syncthreads();
    if (tid < 8) {
        zmn = smn[tid]; zmx = smx[tid];
        #pragma unroll
        for (int o = 4; o > 0; o >>= 1) {
            zmn = fminf(zmn, __shfl_xor_sync(0xffu, zmn, o));
            zmx = fmaxf(zmx, __shfl_xor_sync(0xffu, zmx, o));
        }
        if (tid == 0) {
            atomicMin(&g_zmin_u[bv], f2mono(zmn));
            atomicMax(&g_zmax_u[bv], f2mono(zmx));
        }
    }
}

__global__ __launch_bounds__(THREADS, 1)
void render_kernel(const float* __restrict__ points, float* __restrict__ out) {
    extern __shared__ float simg[];          // NPIX floats (image accumulator)

    const int bv  = blockIdx.x;
    const int b   = bv / NUM_VIEWS;
    const int v   = bv % NUM_VIEWS;
    const int tid = threadIdx.x;

    const float deg2rad = 0.017453292519943295f;
    const float a = (float)(v * 60) * deg2rad;
    const float el_tab[NUM_VIEWS] = {0.f, 30.f, -30.f, 0.f, 0.f, 0.f};
    const float e = el_tab[v] * deg2rad;
    const float ca = cosf(a), sa = sinf(a), ce = cosf(e), se = sinf(e);

    const float4* __restrict__ pb4 =
        (const float4*)(points + (size_t)b * NPTS * 3);

    // zero the shared image (int 0 == float 0.0)
    {
        float4 zv = make_float4(0.f, 0.f, 0.f, 0.f);
        float4* s4 = (float4*)simg;
        for (int i = tid; i < NPIX / 4; i += THREADS) s4[i] = zv;
    }

    // precomputed global min/max for this (b,v)
    const float zmn = mono2f(g_zmin_u[bv]);
    const float zmx = mono2f(g_zmax_u[bv]);
    const float scale = 0.7f / (zmx - zmn + 1e-6f);
    __syncthreads();

    // ---- rotate + branch-free 3x3 splat, double-buffered loads ----
    const float off0 = -2.0f / 224.0f;
    const float off4 =  2.0f / 224.0f;
    int* iimg = (int*)simg;

    {
        float4 c0 = pb4[3 * tid + 0];
        float4 c1 = pb4[3 * tid + 1];
        float4 c2 = pb4[3 * tid + 2];
        #pragma unroll 1
        for (int it = 0; it < NITERS; it++) {
            float4 n0, n1, n2;
            if (it < NITERS - 1) {
                int gn = 3 * (tid + (it + 1) * THREADS);
                n0 = pb4[gn + 0];
                n1 = pb4[gn + 1];
                n2 = pb4[gn + 2];
            }
            float xs[4] = {c0.x, c0.w, c1.z, c2.y};
            float ys[4] = {c0.y, c1.x, c1.w, c2.z};
            float zs[4] = {c0.z, c1.y, c2.x, c2.w};
            #pragma unroll
            for (int k = 0; k < 4; k++) {
                float x = xs[k], y = ys[k], z = zs[k];
                float xr = x * ca - z * sa;
                float zr = x * sa + z * ca;
                float yr = y * ce - zr * se;
                float zf = y * se + zr * ce;

                // identical fp expressions to the reference path (bit-exact
                // pixel coverage)
                int px0 = (int)((xr + off0 + 1.0f) * 0.5f * (float)(IMG - 1));
                int px4 = (int)((xr + off4 + 1.0f) * 0.5f * (float)(IMG - 1));
                int py0 = (int)((yr + off0 + 1.0f) * 0.5f * (float)(IMG - 1));
                int py4 = (int)((yr + off4 + 1.0f) * 0.5f * (float)(IMG - 1));

                int xlo = max(px0, 0), xhi = min(px4, IMG - 1);
                int ylo = max(py0, 0), yhi = min(py4, IMG - 1);
                if (xlo > xhi || ylo > yhi) continue;

                float feat = 0.3f + (zf - zmn) * scale;   // in [0.3, 1.0]
                int fb = __float_as_int(feat);            // positive floats order as ints

                // rect extent <= 3 per axis; min-clamp collapses the unrolled
                // 3x3 onto the exact valid rect (duplicates idempotent under max)
                int x1 = min(xlo + 1, xhi);
                int y1 = min(ylo + 1, yhi);
                int rA = ylo * IMG, rB = y1 * IMG, rC = yhi * IMG;
                atomicMax(&iimg[rA + xlo], fb);
                atomicMax(&iimg[rA + x1 ], fb);
                atomicMax(&iimg[rA + xhi], fb);
                atomicMax(&iimg[rB + xlo], fb);
                atomicMax(&iimg[rB + x1 ], fb);
                atomicMax(&iimg[rB + xhi], fb);
                atomicMax(&iimg[rC + xlo], fb);
                atomicMax(&iimg[rC + x1 ], fb);
                atomicMax(&iimg[rC + xhi], fb);
            }
            c0 = n0; c1 = n1; c2 = n2;
        }
    }
    __syncthreads();

    // ---- Epilogue: broadcast image to 3 channels of out[b][v][c][h][w] ----
    float* __restrict__ ob = out + (size_t)bv * 3 * NPIX;
    float4* __restrict__ ob4 = (float4*)ob;
    const float4* __restrict__ s4 = (const float4*)simg;
    for (int i = tid; i < NPIX / 4; i += THREADS) {
        float4 val = s4[i];
        ob4[i]                = val;
        ob4[i + NPIX / 4]     = val;
        ob4[i + 2 * NPIX / 4] = val;
    }
}

extern "C" void kernel_launch(void* const* d_in, const int* in_sizes, int n_in,
                              void* d_out, int out_size) {
    const float* points = (const float*)d_in[0];
    float* out = (float*)d_out;

    const size_t smem = (size_t)NPIX * sizeof(float);  // 200704 bytes
    cudaFuncSetAttribute(render_kernel,
                         cudaFuncAttributeMaxDynamicSharedMemorySize, (int)smem);

    init_kernel<<<1, 128>>>();
    reduce_kernel<<<NBV * RED_SPLIT, RED_THREADS>>>(points);
    render_kernel<<<NBV, THREADS, smem>>>(points, out);
}